// round 12
// baseline (speedup 1.0000x reference)
#include <cuda_runtime.h>
#include <cstdint>

// ---------------- scratch ----------------
__device__ float g_pool1[512*16*12*36*3];
__device__ float g_pool2[512*32*6*18*3];
__device__ float g_flat [512*64*81];     // (B, D,H,W,C)
__device__ float g_mean [512*64];
__device__ unsigned g_af[72576];         // precomputed tf32 A-fragments (all stages)

// ---------------- tf32 helpers ----------------
__device__ __forceinline__ unsigned f2tf(float f) {
    unsigned r; asm("cvt.rna.tf32.f32 %0, %1;" : "=r"(r) : "f"(f)); return r;
}
__device__ __forceinline__ void mma_tf32(float c[4],
    unsigned a0, unsigned a1, unsigned a2, unsigned a3,
    unsigned b0, unsigned b1)
{
    asm("mma.sync.aligned.m16n8k8.row.col.f32.tf32.tf32.f32 "
        "{%0,%1,%2,%3},{%4,%5,%6,%7},{%8,%9},{%0,%1,%2,%3};"
        : "+f"(c[0]), "+f"(c[1]), "+f"(c[2]), "+f"(c[3])
        : "r"(a0), "r"(a1), "r"(a2), "r"(a3), "r"(b0), "r"(b1));
}

// ---------------- A-fragment precompute (runs once, tiny) ----------------
template<int ICT,int NG,int MT>
__global__ void prep_af(const float* __restrict__ wgt, unsigned* __restrict__ dst, int total)
{
    int idx = blockIdx.x*256 + threadIdx.x;
    if (idx >= total) return;
    constexpr int AFRAG = MT*27*128;
    int i  = idx % AFRAG;
    int zg = idx / AFRAG;          // z*NG + g
    int g  = zg % NG, z = zg / NG;
    int j = i & 3, ln = (i >> 2) & 31, kt = i >> 7;
    int ks = kt % 27, mt = kt / 27;
    int llq = ln & 3, llg = ln >> 2;
    int icl = llq + (j >> 1) * 4;
    int oc  = z*(MT*16) + mt*16 + llg + (j & 1) * 8;
    int ic  = g*8 + icl;
    float v = (ic < ICT) ? __ldg(wgt + ((size_t)oc*ICT + ic)*27 + ks) : 0.f;
    dst[idx] = f2tf(v);
}

// ------- conv3d(3x3x3,pad1)+relu+maxpool(2,2,1), implicit GEMM, tap-major K -------
template<int ICT,int NG,int DIN,int HT,int HIN,int OCB,int OCTOT,int NSUB,bool FLAT>
__global__ __launch_bounds__(256)
void conv_tc(const float* __restrict__ in, const unsigned* __restrict__ af,
             const float* __restrict__ bias, float* __restrict__ outp)
{
    constexpr int ICG = 8, KS = 27;
    constexpr int MT  = OCB/16;
    constexpr int SH  = 5, SD = (HT+2)*5;
    constexpr int SIC_RAW = (DIN+2)*SD;
    constexpr int SIC = ((SIC_RAW + 23)/32)*32 + 8;   // ≡ 8 (mod 32)
    constexpr int N   = DIN*HT*3;
    constexpr int NJ  = (N + NSUB*8 - 1)/(NSUB*8);
    static_assert(NJ <= 8, "one n-block per warp");
    constexpr int NPAD = NJ*NSUB*8;
    constexpr int DOUT = DIN/2, HTO = HT/2, HOUT = HIN/2;
    constexpr int AFRAG = MT*KS*128;
    constexpr int XSW   = ICG*SIC;
    // b1 k-rows lq+4.. : skip crossbar traffic for padded-zero ic rows (last group)
    constexpr int BREM = (ICT % 8 == 0) ? 4 : (ICT % 8) - 4;   // valid b1 lanes: lq < BREM

    extern __shared__ unsigned smu[];
    unsigned* Af = smu;                   // AFRAG words
    unsigned* Xs = smu + AFRAG;           // XSW words
    float*    C  = (float*)smu;           // overlay: used only after final sync

    const int tid  = threadIdx.x;
    const int b    = blockIdx.x;
    const int ht   = blockIdx.y;
    const int ocb0 = blockIdx.z * OCB;
    const int warp = tid >> 5, lane = tid & 31, lq = lane & 3, lg = lane >> 2;

    float acc[MT][NSUB][4];
    #pragma unroll
    for (int mt = 0; mt < MT; mt++)
        #pragma unroll
        for (int s = 0; s < NSUB; s++)
            { acc[mt][s][0]=0.f; acc[mt][s][1]=0.f; acc[mt][s][2]=0.f; acc[mt][s][3]=0.f; }

    // per-warp B base addresses (n-block = warp)
    int bb0[NSUB], bb1[NSUB];
    {
        int n0 = warp * NSUB * 8;
        #pragma unroll
        for (int s = 0; s < NSUB; s++) {
            int n = n0 + s*8 + lg;
            int base = 0;
            if (n < N) {
                int d = n / (HT*3); int r = n % (HT*3);
                base = d*SD + (r/3)*SH + (r%3);
            }
            bb0[s] = base + lq*SIC;
            bb1[s] = base + (lq+4)*SIC;
        }
    }

    // ---- zero Xs once (halo/pad identical across k-groups) ----
    for (int i = tid; i < XSW/4; i += 256) ((uint4*)Xs)[i] = make_uint4(0u,0u,0u,0u);
    __syncthreads();

    #pragma unroll 1
    for (int g = 0; g < NG; g++) {
        if (g) __syncthreads();
        // ---- A fragments: linear copy from precomputed global ----
        {
            const uint4* asrc = (const uint4*)(af + (size_t)(blockIdx.z*NG + g)*AFRAG);
            for (int i = tid; i < AFRAG/4; i += 256) ((uint4*)Af)[i] = asrc[i];
        }
        // ---- X interior rows: 3 coalesced loads per (ic,d,hh) row ----
        {
            const int ICC = (ICT - g*ICG < ICG) ? (ICT - g*ICG) : ICG;
            const int ROWS = ICC * DIN * (HT+2);
            const float* inb = in + ((size_t)b*ICT + g*ICG) * DIN * HIN * 3;
            for (int r = tid; r < ROWS; r += 256) {
                int ic  = r / (DIN*(HT+2));
                int rem = r % (DIN*(HT+2));
                int d   = rem / (HT+2);
                int hh  = rem % (HT+2);
                int h   = ht*HT + hh - 1;
                if ((unsigned)h < (unsigned)HIN) {
                    const float* src = inb + ((size_t)ic*DIN + d)*(HIN*3) + h*3;
                    unsigned* dstp = Xs + ic*SIC + (d+1)*SD + hh*5 + 1;
                    dstp[0] = f2tf(src[0]);
                    dstp[1] = f2tf(src[1]);
                    dstp[2] = f2tf(src[2]);
                }
            }
        }
        __syncthreads();

        const bool lastg = (g == NG-1);
        if (warp < NJ) {
            const uint4* Afr = (const uint4*)Af + lane;
            #pragma unroll
            for (int ks = 0; ks < KS; ks++) {
                uint4 a[MT];
                #pragma unroll
                for (int mt = 0; mt < MT; mt++) a[mt] = Afr[(mt*KS + ks)*32];
                const int toff = (ks/9)*SD + ((ks/3)%3)*SH + (ks%3);
                #pragma unroll
                for (int s = 0; s < NSUB; s++) {
                    unsigned b0 = Xs[bb0[s] + toff];
                    unsigned b1 = 0u;
                    if (BREM >= 4 || !lastg || lq < BREM) b1 = Xs[bb1[s] + toff];
                    #pragma unroll
                    for (int mt = 0; mt < MT; mt++)
                        mma_tf32(acc[mt][s], a[mt].x, a[mt].y, a[mt].z, a[mt].w, b0, b1);
                }
            }
        }
    }
    __syncthreads();   // all Af/Xs reads done -> C may overlay

    if (warp < NJ) {
        int n0 = warp * NSUB * 8;
        #pragma unroll
        for (int mt = 0; mt < MT; mt++) {
            int m0 = mt*16;
            #pragma unroll
            for (int s = 0; s < NSUB; s++) {
                int nn = n0 + s*8 + 2*lq;
                C[(m0+lg  )*NPAD + nn  ] = acc[mt][s][0];
                C[(m0+lg  )*NPAD + nn+1] = acc[mt][s][1];
                C[(m0+lg+8)*NPAD + nn  ] = acc[mt][s][2];
                C[(m0+lg+8)*NPAD + nn+1] = acc[mt][s][3];
            }
        }
    }
    __syncthreads();

    // ---- pool(2,2,1) + bias + relu + store ----
    constexpr int TOT = OCB * DOUT * HTO * 3;
    for (int i = tid; i < TOT; i += 256) {
        int oc = i / (DOUT*HTO*3); int r = i % (DOUT*HTO*3);
        int dp = r / (HTO*3); int r2 = r % (HTO*3); int hp = r2/3, w = r2%3;
        const float* Cr = C + (size_t)oc*NPAD;
        int n00 = ((2*dp)*HT + 2*hp)*3 + w;
        float v = fmaxf(fmaxf(Cr[n00], Cr[n00+3]),
                        fmaxf(Cr[n00+HT*3], Cr[n00+HT*3+3]));
        int ocg = ocb0 + oc;
        v = fmaxf(v + __ldg(bias + ocg), 0.f);
        int hpg = ht*HTO + hp;
        if (FLAT)
            outp[(size_t)b*(DOUT*HOUT*3*OCTOT) + ((dp*HOUT + hpg)*3 + w)*OCTOT + ocg] = v;
        else
            outp[((size_t)b*OCTOT + ocg)*(DOUT*HOUT*3) + (dp*HOUT + hpg)*3 + w] = v;
    }
}

// ---------------- mean over the 81 spatial positions ----------------
__global__ void mean_kernel()
{
    int b = blockIdx.x, c = threadIdx.x;
    const float* f = g_flat + (size_t)b * 5184 + c;
    float s = 0.f;
    #pragma unroll
    for (int p = 0; p < 81; p++) s += f[p * 64];
    g_mean[b * 64 + c] = s * (1.f / 81.f);
}

// ---------------- smem-tiled matvec, 4 rows: out[n=t][r] += W[n][k]*X[k][r] ----------------
template<int K, int KT>
__device__ __forceinline__ void matvec4(const float* __restrict__ W,
                                        const float* __restrict__ Xsh,
                                        float* __restrict__ Wsh,
                                        float acc[4], int t)
{
    constexpr int RS = KT + 4;
    constexpr int QP = KT / 4;
    for (int kt = 0; kt < K; kt += KT) {
        __syncthreads();
        #pragma unroll
        for (int i = 0; i < QP; i++) {
            int idx = t + i * 256;
            int n   = idx / QP;
            int kq  = idx % QP;
            *(float4*)(Wsh + n * RS + kq * 4) =
                *(const float4*)(W + (size_t)n * K + kt + kq * 4);
        }
        __syncthreads();
        #pragma unroll
        for (int kk = 0; kk < KT; kk += 4) {
            float4 wv = *(const float4*)(Wsh + t * RS + kk);
            float4 x0 = *(const float4*)(Xsh + (kt + kk + 0) * 4);
            float4 x1 = *(const float4*)(Xsh + (kt + kk + 1) * 4);
            float4 x2 = *(const float4*)(Xsh + (kt + kk + 2) * 4);
            float4 x3 = *(const float4*)(Xsh + (kt + kk + 3) * 4);
            acc[0] += wv.x * x0.x; acc[1] += wv.x * x0.y; acc[2] += wv.x * x0.z; acc[3] += wv.x * x0.w;
            acc[0] += wv.y * x1.x; acc[1] += wv.y * x1.y; acc[2] += wv.y * x1.z; acc[3] += wv.y * x1.w;
            acc[0] += wv.z * x2.x; acc[1] += wv.z * x2.y; acc[2] += wv.z * x2.z; acc[3] += wv.z * x2.w;
            acc[0] += wv.w * x3.x; acc[1] += wv.w * x3.y; acc[2] += wv.w * x3.z; acc[3] += wv.w * x3.w;
        }
    }
}

// ---------------- smem-tiled matvec, 8 rows ----------------
template<int K, int KT>
__device__ __forceinline__ void matvec8(const float* __restrict__ W,
                                        const float* __restrict__ Xsh,
                                        float* __restrict__ Wsh,
                                        float acc[8], int t)
{
    constexpr int RS = KT + 4;
    constexpr int QP = KT / 4;
    for (int kt = 0; kt < K; kt += KT) {
        __syncthreads();
        #pragma unroll
        for (int i = 0; i < QP; i++) {
            int idx = t + i * 256;
            int n   = idx / QP;
            int kq  = idx % QP;
            *(float4*)(Wsh + n * RS + kq * 4) =
                *(const float4*)(W + (size_t)n * K + kt + kq * 4);
        }
        __syncthreads();
        #pragma unroll
        for (int kk = 0; kk < KT; kk += 4) {
            float4 wv = *(const float4*)(Wsh + t * RS + kk);
            #pragma unroll
            for (int q = 0; q < 4; q++) {
                float w = (q==0) ? wv.x : (q==1) ? wv.y : (q==2) ? wv.z : wv.w;
                const float4* xp = (const float4*)(Xsh + (kt + kk + q) * 8);
                float4 xa = xp[0], xb = xp[1];
                acc[0] += w*xa.x; acc[1] += w*xa.y; acc[2] += w*xa.z; acc[3] += w*xa.w;
                acc[4] += w*xb.x; acc[5] += w*xb.y; acc[6] += w*xb.z; acc[7] += w*xb.w;
            }
        }
    }
}

// ---------------- fused RNN decoder (8 rows/block) + linear head (co-scheduled) ----------------
// blocks 0..63: RNN (8 batch rows each).  blocks 64..191: head (4 rows each).
__global__ __launch_bounds__(256, 1)
void tail_kernel(const float* __restrict__ whh1, const float* __restrict__ wih2,
                 const float* __restrict__ whh2,
                 const float* __restrict__ w_init_h,  const float* __restrict__ b_init_h,
                 const float* __restrict__ w_init_h2, const float* __restrict__ b_init_h2,
                 const float* __restrict__ wih1, const float* __restrict__ bih1,
                 const float* __restrict__ bhh1,
                 const float* __restrict__ bih2, const float* __restrict__ bhh2,
                 const float* __restrict__ w_fc, const float* __restrict__ b_fc,
                 const float* __restrict__ w_lin1, const float* __restrict__ b_lin1,
                 const float* __restrict__ w_lin2, const float* __restrict__ b_lin2,
                 float* __restrict__ preds, float* __restrict__ outc)
{
    extern __shared__ float sm[];
    const int t = threadIdx.x;

    if (blockIdx.x < 64) {
        // ================= RNN path (8 rows) =================
        float* me   = sm;            //  64*8 = 512
        float* hS   = sm + 512;      // 256*8 = 2048
        float* h2S  = sm + 2560;
        float* ihcS = sm + 4608;
        float* hnS  = sm + 6656;
        float* Wsh  = sm + 8704;     // 256*68 = 17408

        const int r0 = blockIdx.x * 8;

        for (int idx = t; idx < 512; idx += 256) {
            int r = idx & 7, k = idx >> 3;
            me[k*8 + r] = g_mean[(size_t)(r0 + r) * 64 + k];
        }

        float a[8] = {0,0,0,0,0,0,0,0};
        matvec8<64,64>(w_init_h, me, Wsh, a, t);
        float c[8] = {0,0,0,0,0,0,0,0};
        matvec8<64,64>(wih1, me, Wsh, c, t);
        {
            float bh = __ldg(b_init_h + t);
            float bi = __ldg(bih1 + t) + __ldg(bhh1 + t);
            #pragma unroll
            for (int r = 0; r < 8; r++) { hS[t*8 + r] = a[r] + bh; ihcS[t*8 + r] = c[r] + bi; }
        }
        float a2[8] = {0,0,0,0,0,0,0,0};
        matvec8<256,64>(w_init_h2, hS, Wsh, a2, t);
        {
            float b2 = __ldg(b_init_h2 + t);
            #pragma unroll
            for (int r = 0; r < 8; r++) h2S[t*8 + r] = a2[r] + b2;
        }
        const float bi2 = __ldg(bih2 + t) + __ldg(bhh2 + t);
        const float bfc = __ldg(b_fc);

        for (int step = 0; step < 23; ++step) {
            float ah[8] = {0,0,0,0,0,0,0,0};
            matvec8<256,64>(whh1, hS, Wsh, ah, t);
            #pragma unroll
            for (int r = 0; r < 8; r++) hnS[t*8 + r] = tanhf(ihcS[t*8 + r] + ah[r]);
            float u[8] = {0,0,0,0,0,0,0,0};
            matvec8<256,64>(wih2, hnS, Wsh, u, t);
            float v[8] = {0,0,0,0,0,0,0,0};
            matvec8<256,64>(whh2, h2S, Wsh, v, t);
            __syncthreads();
            #pragma unroll
            for (int r = 0; r < 8; r++) {
                h2S[t*8 + r] = tanhf(u[r] + v[r] + bi2);
                hS[t*8 + r]  = hnS[t*8 + r];
            }
            __syncthreads();
            {
                int r = t >> 5, lane = t & 31;
                float s = 0.f;
                #pragma unroll
                for (int k = lane; k < 256; k += 32) s += __ldg(w_fc + k) * h2S[k*8 + r];
                #pragma unroll
                for (int off = 16; off; off >>= 1) s += __shfl_down_sync(0xffffffffu, s, off);
                if (lane == 0) preds[(size_t)(r0 + r) * 23 + step] = s + bfc;
            }
        }
    } else {
        // ================= head path (4 rows) =================
        float* xS  = sm;             // 5184*4
        float* thS = sm + 20736;     // 1024
        float* Wsh = sm + 21760;     // 256*68
        const int r0 = (blockIdx.x - 64) * 4;

        for (int idx = t; idx < 4 * 5184; idx += 256) {
            int r = idx / 5184, k = idx % 5184;
            xS[k*4 + r] = g_flat[(size_t)(r0 + r) * 5184 + k];
        }

        float a[4] = {0,0,0,0};
        matvec4<5184,64>(w_lin1, xS, Wsh, a, t);
        float bl = __ldg(b_lin1 + t);
        #pragma unroll
        for (int r = 0; r < 4; r++) thS[t*4 + r] = tanhf(a[r] + bl);
        __syncthreads();

        if (t < 48) {
            int n = t % 12, r = t / 12;
            float s = 0.f;
            #pragma unroll 4
            for (int k = 0; k < 256; k++) s += __ldg(w_lin2 + n*256 + k) * thS[k*4 + r];
            outc[(size_t)(r0 + r) * 12 + n] = s + __ldg(b_lin2 + n);
        }
    }
}

// ---------------- launch ----------------
extern "C" void kernel_launch(void* const* d_in, const int* in_sizes, int n_in,
                              void* d_out, int out_size)
{
    const float* x    = (const float*)d_in[0];
    const float* w1   = (const float*)d_in[1];
    const float* b1   = (const float*)d_in[2];
    const float* w2   = (const float*)d_in[3];
    const float* b2   = (const float*)d_in[4];
    const float* w3   = (const float*)d_in[5];
    const float* b3   = (const float*)d_in[6];
    const float* wih1 = (const float*)d_in[7];
    const float* whh1 = (const float*)d_in[8];
    const float* bih1 = (const float*)d_in[9];
    const float* bhh1 = (const float*)d_in[10];
    const float* wih2 = (const float*)d_in[11];
    const float* whh2 = (const float*)d_in[12];
    const float* bih2 = (const float*)d_in[13];
    const float* bhh2 = (const float*)d_in[14];
    const float* w_init_h  = (const float*)d_in[15];
    const float* b_init_h  = (const float*)d_in[16];
    const float* w_init_h2 = (const float*)d_in[17];
    const float* b_init_h2 = (const float*)d_in[18];
    const float* w_fc  = (const float*)d_in[19];
    const float* b_fc  = (const float*)d_in[20];
    const float* w_lin1 = (const float*)d_in[21];
    const float* b_lin1 = (const float*)d_in[22];
    const float* w_lin2 = (const float*)d_in[23];
    const float* b_lin2 = (const float*)d_in[24];
    float* out = (float*)d_out;

    float *p1, *p2, *pf;
    unsigned* af;
    cudaGetSymbolAddress((void**)&p1, g_pool1);
    cudaGetSymbolAddress((void**)&p2, g_pool2);
    cudaGetSymbolAddress((void**)&pf, g_flat);
    cudaGetSymbolAddress((void**)&af, g_af);

    // ---- A-fragment precompute (launch idx 0..2) ----
    prep_af<6,1,1><<<14, 256>>>(w1, af,          3456);
    prep_af<16,2,2><<<54, 256>>>(w2, af + 3456,  13824);
    prep_af<32,4,2><<<216,256>>>(w3, af + 17280, 55296);

    // stage 1 (idx 3, profiled): ICT=6, NG=1, D24, HT8, H72, OC16, NSUB=9  smem=56064B
    auto k1 = conv_tc<6,1,24,8,72,16,16,9,false>;
    cudaFuncSetAttribute(k1, cudaFuncAttributeMaxDynamicSharedMemorySize, 56064);
    k1<<<dim3(512,9,1), 256, 56064>>>(x, af, b1, p1);

    // stage 2: ICT=16, NG=2, D12, HT12, H36, OC32, NSUB=7  smem=59648B
    auto k2 = conv_tc<16,2,12,12,36,32,32,7,false>;
    cudaFuncSetAttribute(k2, cudaFuncAttributeMaxDynamicSharedMemorySize, 59648);
    k2<<<dim3(512,3,1), 256, 59648>>>(p1, af + 3456, b2, p2);

    // stage 3: ICT=32, NG=4, D6, HT18, H18, OC 2x32, NSUB=6  smem=53504B
    auto k3 = conv_tc<32,4,6,18,18,32,64,6,true>;
    cudaFuncSetAttribute(k3, cudaFuncAttributeMaxDynamicSharedMemorySize, 53504);
    k3<<<dim3(512,1,2), 256, 53504>>>(p2, af + 17280, b3, pf);

    mean_kernel<<<512, 64>>>();

    // fused RNN (64 blocks, 8 rows) + head (128 blocks): 192 blocks co-scheduled
    cudaFuncSetAttribute(tail_kernel, cudaFuncAttributeMaxDynamicSharedMemorySize, 156672);
    tail_kernel<<<192, 256, 156672>>>(whh1, wih2, whh2,
                                      w_init_h, b_init_h, w_init_h2, b_init_h2,
                                      wih1, bih1, bhh1, bih2, bhh2,
                                      w_fc, b_fc,
                                      w_lin1, b_lin1, w_lin2, b_lin2,
                                      out, out + 512 * 23);
}

// round 13
// speedup vs baseline: 1.0451x; 1.0451x over previous
#include <cuda_runtime.h>
#include <cstdint>

// ---------------- scratch ----------------
__device__ float g_pool1[512*16*12*36*3];
__device__ float g_pool2[512*32*6*18*3];
__device__ float g_flat [512*64*81];     // (B, D,H,W,C)
__device__ float g_mean [512*64];
__device__ unsigned g_af[72576];         // precomputed tf32 A-fragments (all stages)

// ---------------- tf32 helpers ----------------
__device__ __forceinline__ unsigned f2tf(float f) {
    unsigned r; asm("cvt.rna.tf32.f32 %0, %1;" : "=r"(r) : "f"(f)); return r;
}
__device__ __forceinline__ void mma_tf32(float c[4],
    unsigned a0, unsigned a1, unsigned a2, unsigned a3,
    unsigned b0, unsigned b1)
{
    asm("mma.sync.aligned.m16n8k8.row.col.f32.tf32.tf32.f32 "
        "{%0,%1,%2,%3},{%4,%5,%6,%7},{%8,%9},{%0,%1,%2,%3};"
        : "+f"(c[0]), "+f"(c[1]), "+f"(c[2]), "+f"(c[3])
        : "r"(a0), "r"(a1), "r"(a2), "r"(a3), "r"(b0), "r"(b1));
}

// ---------------- A-fragment precompute (runs once, tiny) ----------------
template<int ICT,int NG,int MT>
__global__ void prep_af(const float* __restrict__ wgt, unsigned* __restrict__ dst, int total)
{
    int idx = blockIdx.x*256 + threadIdx.x;
    if (idx >= total) return;
    constexpr int AFRAG = MT*27*128;
    int i  = idx % AFRAG;
    int zg = idx / AFRAG;          // z*NG + g
    int g  = zg % NG, z = zg / NG;
    int j = i & 3, ln = (i >> 2) & 31, kt = i >> 7;
    int ks = kt % 27, mt = kt / 27;
    int llq = ln & 3, llg = ln >> 2;
    int icl = llq + (j >> 1) * 4;
    int oc  = z*(MT*16) + mt*16 + llg + (j & 1) * 8;
    int ic  = g*8 + icl;
    float v = (ic < ICT) ? __ldg(wgt + ((size_t)oc*ICT + ic)*27 + ks) : 0.f;
    dst[idx] = f2tf(v);
}

// ------- conv3d(3x3x3,pad1)+relu+maxpool(2,2,1), implicit GEMM, tap-major K -------
template<int ICT,int NG,int DIN,int HT,int HIN,int OCB,int OCTOT,int NSUB,bool FLAT>
__global__ __launch_bounds__(256)
void conv_tc(const float* __restrict__ in, const unsigned* __restrict__ af,
             const float* __restrict__ bias, float* __restrict__ outp)
{
    constexpr int ICG = 8, KS = 27;
    constexpr int MT  = OCB/16;
    constexpr int SH  = 5, SD = (HT+2)*5;
    constexpr int SIC_RAW = (DIN+2)*SD;
    constexpr int SIC = ((SIC_RAW + 23)/32)*32 + 8;   // ≡ 8 (mod 32)
    constexpr int N   = DIN*HT*3;
    constexpr int NJ  = (N + NSUB*8 - 1)/(NSUB*8);
    static_assert(NJ <= 8, "one n-block per warp");
    constexpr int NPAD = NJ*NSUB*8;
    constexpr int DOUT = DIN/2, HTO = HT/2, HOUT = HIN/2;
    constexpr int AFRAG = MT*KS*128;
    constexpr int XSW   = ICG*SIC;

    extern __shared__ unsigned smu[];
    unsigned* Af = smu;                   // AFRAG words
    unsigned* Xs = smu + AFRAG;           // XSW words
    float*    C  = (float*)smu;           // overlay: used only after final sync

    const int tid  = threadIdx.x;
    const int b    = blockIdx.x;
    const int ht   = blockIdx.y;
    const int ocb0 = blockIdx.z * OCB;
    const int warp = tid >> 5, lane = tid & 31, lq = lane & 3, lg = lane >> 2;

    float acc[MT][NSUB][4];
    #pragma unroll
    for (int mt = 0; mt < MT; mt++)
        #pragma unroll
        for (int s = 0; s < NSUB; s++)
            { acc[mt][s][0]=0.f; acc[mt][s][1]=0.f; acc[mt][s][2]=0.f; acc[mt][s][3]=0.f; }

    // per-warp B base addresses (n-block = warp)
    int bb0[NSUB], bb1[NSUB];
    {
        int n0 = warp * NSUB * 8;
        #pragma unroll
        for (int s = 0; s < NSUB; s++) {
            int n = n0 + s*8 + lg;
            int base = 0;
            if (n < N) {
                int d = n / (HT*3); int r = n % (HT*3);
                base = d*SD + (r/3)*SH + (r%3);
            }
            bb0[s] = base + lq*SIC;
            bb1[s] = base + (lq+4)*SIC;
        }
    }

    // ---- zero Xs once (halo/pad identical across k-groups) ----
    for (int i = tid; i < XSW/4; i += 256) ((uint4*)Xs)[i] = make_uint4(0u,0u,0u,0u);
    __syncthreads();

    #pragma unroll 1
    for (int g = 0; g < NG; g++) {
        if (g) __syncthreads();
        // ---- A fragments: linear copy from precomputed global ----
        {
            const uint4* asrc = (const uint4*)(af + (size_t)(blockIdx.z*NG + g)*AFRAG);
            for (int i = tid; i < AFRAG/4; i += 256) ((uint4*)Af)[i] = asrc[i];
        }
        // ---- X interior rows: 3 coalesced loads per (ic,d,hh) row ----
        {
            const int ICC = (ICT - g*ICG < ICG) ? (ICT - g*ICG) : ICG;
            const int ROWS = ICC * DIN * (HT+2);
            const float* inb = in + ((size_t)b*ICT + g*ICG) * DIN * HIN * 3;
            for (int r = tid; r < ROWS; r += 256) {
                int ic  = r / (DIN*(HT+2));
                int rem = r % (DIN*(HT+2));
                int d   = rem / (HT+2);
                int hh  = rem % (HT+2);
                int h   = ht*HT + hh - 1;
                if ((unsigned)h < (unsigned)HIN) {
                    const float* src = inb + ((size_t)ic*DIN + d)*(HIN*3) + h*3;
                    unsigned* dstp = Xs + ic*SIC + (d+1)*SD + hh*5 + 1;
                    dstp[0] = f2tf(src[0]);
                    dstp[1] = f2tf(src[1]);
                    dstp[2] = f2tf(src[2]);
                }
            }
        }
        __syncthreads();

        if (warp < NJ) {
            const uint4* Afr = (const uint4*)Af + lane;
            #pragma unroll
            for (int ks = 0; ks < KS; ks++) {
                uint4 a[MT];
                #pragma unroll
                for (int mt = 0; mt < MT; mt++) a[mt] = Afr[(mt*KS + ks)*32];
                const int toff = (ks/9)*SD + ((ks/3)%3)*SH + (ks%3);
                #pragma unroll
                for (int s = 0; s < NSUB; s++) {
                    unsigned b0 = Xs[bb0[s] + toff];
                    unsigned b1 = Xs[bb1[s] + toff];
                    #pragma unroll
                    for (int mt = 0; mt < MT; mt++)
                        mma_tf32(acc[mt][s], a[mt].x, a[mt].y, a[mt].z, a[mt].w, b0, b1);
                }
            }
        }
    }
    __syncthreads();   // all Af/Xs reads done -> C may overlay

    if (warp < NJ) {
        int n0 = warp * NSUB * 8;
        #pragma unroll
        for (int mt = 0; mt < MT; mt++) {
            int m0 = mt*16;
            #pragma unroll
            for (int s = 0; s < NSUB; s++) {
                int nn = n0 + s*8 + 2*lq;
                C[(m0+lg  )*NPAD + nn  ] = acc[mt][s][0];
                C[(m0+lg  )*NPAD + nn+1] = acc[mt][s][1];
                C[(m0+lg+8)*NPAD + nn  ] = acc[mt][s][2];
                C[(m0+lg+8)*NPAD + nn+1] = acc[mt][s][3];
            }
        }
    }
    __syncthreads();

    // ---- pool(2,2,1) + bias + relu + store ----
    constexpr int TOT = OCB * DOUT * HTO * 3;
    for (int i = tid; i < TOT; i += 256) {
        int oc = i / (DOUT*HTO*3); int r = i % (DOUT*HTO*3);
        int dp = r / (HTO*3); int r2 = r % (HTO*3); int hp = r2/3, w = r2%3;
        const float* Cr = C + (size_t)oc*NPAD;
        int n00 = ((2*dp)*HT + 2*hp)*3 + w;
        float v = fmaxf(fmaxf(Cr[n00], Cr[n00+3]),
                        fmaxf(Cr[n00+HT*3], Cr[n00+HT*3+3]));
        int ocg = ocb0 + oc;
        v = fmaxf(v + __ldg(bias + ocg), 0.f);
        int hpg = ht*HTO + hp;
        if (FLAT)
            outp[(size_t)b*(DOUT*HOUT*3*OCTOT) + ((dp*HOUT + hpg)*3 + w)*OCTOT + ocg] = v;
        else
            outp[((size_t)b*OCTOT + ocg)*(DOUT*HOUT*3) + (dp*HOUT + hpg)*3 + w] = v;
    }
}

// ---------------- mean over the 81 spatial positions ----------------
__global__ void mean_kernel()
{
    int b = blockIdx.x, c = threadIdx.x;
    const float* f = g_flat + (size_t)b * 5184 + c;
    float s = 0.f;
    #pragma unroll
    for (int p = 0; p < 81; p++) s += f[p * 64];
    g_mean[b * 64 + c] = s * (1.f / 81.f);
}

// ---------------- smem-tiled matvec: out[n=t][r=0..3] += W[n][k] * X[k][r] ----------------
template<int K, int KT>
__device__ __forceinline__ void matvec4(const float* __restrict__ W,
                                        const float* __restrict__ Xsh,
                                        float* __restrict__ Wsh,
                                        float acc[4], int t)
{
    constexpr int RS = KT + 4;
    constexpr int QP = KT / 4;
    for (int kt = 0; kt < K; kt += KT) {
        __syncthreads();
        #pragma unroll
        for (int i = 0; i < QP; i++) {
            int idx = t + i * 256;
            int n   = idx / QP;
            int kq  = idx % QP;
            *(float4*)(Wsh + n * RS + kq * 4) =
                *(const float4*)(W + (size_t)n * K + kt + kq * 4);
        }
        __syncthreads();
        #pragma unroll
        for (int kk = 0; kk < KT; kk += 4) {
            float4 wv = *(const float4*)(Wsh + t * RS + kk);
            float4 x0 = *(const float4*)(Xsh + (kt + kk + 0) * 4);
            float4 x1 = *(const float4*)(Xsh + (kt + kk + 1) * 4);
            float4 x2 = *(const float4*)(Xsh + (kt + kk + 2) * 4);
            float4 x3 = *(const float4*)(Xsh + (kt + kk + 3) * 4);
            acc[0] += wv.x * x0.x; acc[1] += wv.x * x0.y; acc[2] += wv.x * x0.z; acc[3] += wv.x * x0.w;
            acc[0] += wv.y * x1.x; acc[1] += wv.y * x1.y; acc[2] += wv.y * x1.z; acc[3] += wv.y * x1.w;
            acc[0] += wv.z * x2.x; acc[1] += wv.z * x2.y; acc[2] += wv.z * x2.z; acc[3] += wv.z * x2.w;
            acc[0] += wv.w * x3.x; acc[1] += wv.w * x3.y; acc[2] += wv.w * x3.z; acc[3] += wv.w * x3.w;
        }
    }
}

// ---------------- fused RNN decoder + linear head (co-scheduled) ----------------
// blocks 0..127: RNN (4 batch rows each).  blocks 128..255: head (4 rows each).
__global__ __launch_bounds__(256, 1)
void tail_kernel(const float* __restrict__ whh1, const float* __restrict__ wih2,
                 const float* __restrict__ whh2,
                 const float* __restrict__ w_init_h,  const float* __restrict__ b_init_h,
                 const float* __restrict__ w_init_h2, const float* __restrict__ b_init_h2,
                 const float* __restrict__ wih1, const float* __restrict__ bih1,
                 const float* __restrict__ bhh1,
                 const float* __restrict__ bih2, const float* __restrict__ bhh2,
                 const float* __restrict__ w_fc, const float* __restrict__ b_fc,
                 const float* __restrict__ w_lin1, const float* __restrict__ b_lin1,
                 const float* __restrict__ w_lin2, const float* __restrict__ b_lin2,
                 float* __restrict__ preds, float* __restrict__ outc)
{
    extern __shared__ float sm[];
    const int t = threadIdx.x;

    if (blockIdx.x < 128) {
        // ================= RNN path =================
        float* me   = sm;
        float* hS   = sm + 256;
        float* h2S  = sm + 1280;
        float* ihcS = sm + 2304;
        float* hnS  = sm + 3328;
        float* Wsh  = sm + 4352;     // 256*68 floats

        const int r0 = blockIdx.x * 4;

        { int r = t & 3, k = t >> 2;
          me[k*4 + r] = g_mean[(size_t)(r0 + r) * 64 + k]; }

        float a[4] = {0,0,0,0};
        matvec4<64,64>(w_init_h, me, Wsh, a, t);
        float c[4] = {0,0,0,0};
        matvec4<64,64>(wih1, me, Wsh, c, t);
        {
            float bh = __ldg(b_init_h + t);
            float bi = __ldg(bih1 + t) + __ldg(bhh1 + t);
            #pragma unroll
            for (int r = 0; r < 4; r++) { hS[t*4 + r] = a[r] + bh; ihcS[t*4 + r] = c[r] + bi; }
        }
        float a2[4] = {0,0,0,0};
        matvec4<256,64>(w_init_h2, hS, Wsh, a2, t);
        {
            float b2 = __ldg(b_init_h2 + t);
            #pragma unroll
            for (int r = 0; r < 4; r++) h2S[t*4 + r] = a2[r] + b2;
        }
        const float bi2 = __ldg(bih2 + t) + __ldg(bhh2 + t);
        const float bfc = __ldg(b_fc);

        for (int step = 0; step < 23; ++step) {
            float ah[4] = {0,0,0,0};
            matvec4<256,64>(whh1, hS, Wsh, ah, t);
            #pragma unroll
            for (int r = 0; r < 4; r++) hnS[t*4 + r] = tanhf(ihcS[t*4 + r] + ah[r]);
            float u[4] = {0,0,0,0};
            matvec4<256,64>(wih2, hnS, Wsh, u, t);
            float v[4] = {0,0,0,0};
            matvec4<256,64>(whh2, h2S, Wsh, v, t);
            __syncthreads();
            #pragma unroll
            for (int r = 0; r < 4; r++) {
                h2S[t*4 + r] = tanhf(u[r] + v[r] + bi2);
                hS[t*4 + r]  = hnS[t*4 + r];
            }
            __syncthreads();
            if (t < 128) {
                int r = t >> 5, lane = t & 31;
                float s = 0.f;
                #pragma unroll
                for (int k = lane; k < 256; k += 32) s += __ldg(w_fc + k) * h2S[k*4 + r];
                #pragma unroll
                for (int off = 16; off; off >>= 1) s += __shfl_down_sync(0xffffffffu, s, off);
                if (lane == 0) preds[(size_t)(r0 + r) * 23 + step] = s + bfc;
            }
        }
    } else {
        // ================= head path =================
        float* xS  = sm;             // 5184*4
        float* thS = sm + 20736;     // 1024
        float* Wsh = sm + 21760;     // 256*68
        const int r0 = (blockIdx.x - 128) * 4;

        for (int idx = t; idx < 4 * 5184; idx += 256) {
            int r = idx / 5184, k = idx % 5184;
            xS[k*4 + r] = g_flat[(size_t)(r0 + r) * 5184 + k];
        }

        float a[4] = {0,0,0,0};
        matvec4<5184,64>(w_lin1, xS, Wsh, a, t);
        float bl = __ldg(b_lin1 + t);
        #pragma unroll
        for (int r = 0; r < 4; r++) thS[t*4 + r] = tanhf(a[r] + bl);
        __syncthreads();

        if (t < 48) {
            int n = t % 12, r = t / 12;
            float s = 0.f;
            #pragma unroll 4
            for (int k = 0; k < 256; k++) s += __ldg(w_lin2 + n*256 + k) * thS[k*4 + r];
            outc[(size_t)(r0 + r) * 12 + n] = s + __ldg(b_lin2 + n);
        }
    }
}

// ---------------- launch ----------------
extern "C" void kernel_launch(void* const* d_in, const int* in_sizes, int n_in,
                              void* d_out, int out_size)
{
    const float* x    = (const float*)d_in[0];
    const float* w1   = (const float*)d_in[1];
    const float* b1   = (const float*)d_in[2];
    const float* w2   = (const float*)d_in[3];
    const float* b2   = (const float*)d_in[4];
    const float* w3   = (const float*)d_in[5];
    const float* b3   = (const float*)d_in[6];
    const float* wih1 = (const float*)d_in[7];
    const float* whh1 = (const float*)d_in[8];
    const float* bih1 = (const float*)d_in[9];
    const float* bhh1 = (const float*)d_in[10];
    const float* wih2 = (const float*)d_in[11];
    const float* whh2 = (const float*)d_in[12];
    const float* bih2 = (const float*)d_in[13];
    const float* bhh2 = (const float*)d_in[14];
    const float* w_init_h  = (const float*)d_in[15];
    const float* b_init_h  = (const float*)d_in[16];
    const float* w_init_h2 = (const float*)d_in[17];
    const float* b_init_h2 = (const float*)d_in[18];
    const float* w_fc  = (const float*)d_in[19];
    const float* b_fc  = (const float*)d_in[20];
    const float* w_lin1 = (const float*)d_in[21];
    const float* b_lin1 = (const float*)d_in[22];
    const float* w_lin2 = (const float*)d_in[23];
    const float* b_lin2 = (const float*)d_in[24];
    float* out = (float*)d_out;

    float *p1, *p2, *pf;
    unsigned* af;
    cudaGetSymbolAddress((void**)&p1, g_pool1);
    cudaGetSymbolAddress((void**)&p2, g_pool2);
    cudaGetSymbolAddress((void**)&pf, g_flat);
    cudaGetSymbolAddress((void**)&af, g_af);

    // launch order reshuffled so stage-2 conv is profiled (index 3);
    // each prep still precedes its stage.
    // idx 0: prep stage-1 A-fragments
    prep_af<6,1,1><<<14, 256>>>(w1, af, 3456);

    // idx 1: stage 1: ICT=6, NG=1, D24, HT8, H72, OC16, NSUB=9  smem=56064B -> 4 CTA/SM
    auto k1 = conv_tc<6,1,24,8,72,16,16,9,false>;
    cudaFuncSetAttribute(k1, cudaFuncAttributeMaxDynamicSharedMemorySize, 56064);
    k1<<<dim3(512,9,1), 256, 56064>>>(x, af, b1, p1);

    // idx 2: prep stage-2 A-fragments
    prep_af<16,2,2><<<54, 256>>>(w2, af + 3456, 13824);

    // idx 3 (profiled): stage 2: ICT=16, NG=2, D12, HT12, H36, OC32, NSUB=7  smem=59648B
    auto k2 = conv_tc<16,2,12,12,36,32,32,7,false>;
    cudaFuncSetAttribute(k2, cudaFuncAttributeMaxDynamicSharedMemorySize, 59648);
    k2<<<dim3(512,3,1), 256, 59648>>>(p1, af + 3456, b2, p2);

    // idx 4: prep stage-3 A-fragments
    prep_af<32,4,2><<<216,256>>>(w3, af + 17280, 55296);

    // idx 5: stage 3: ICT=32, NG=4, D6, HT18, H18, OC 2x32, NSUB=6  smem=53504B
    auto k3 = conv_tc<32,4,6,18,18,32,64,6,true>;
    cudaFuncSetAttribute(k3, cudaFuncAttributeMaxDynamicSharedMemorySize, 53504);
    k3<<<dim3(512,1,2), 256, 53504>>>(p2, af + 17280, b3, pf);

    // idx 6: mean
    mean_kernel<<<512, 64>>>();

    // idx 7: fused RNN + head: 256 blocks co-scheduled
    cudaFuncSetAttribute(tail_kernel, cudaFuncAttributeMaxDynamicSharedMemorySize, 156672);
    tail_kernel<<<256, 256, 156672>>>(whh1, wih2, whh2,
                                      w_init_h, b_init_h, w_init_h2, b_init_h2,
                                      wih1, bih1, bhh1, bih2, bhh2,
                                      w_fc, b_fc,
                                      w_lin1, b_lin1, w_lin2, b_lin2,
                                      out, out + 512 * 23);
}

// round 14
// speedup vs baseline: 1.0521x; 1.0067x over previous
#include <cuda_runtime.h>
#include <cstdint>

// ---------------- scratch ----------------
__device__ float g_pool1[512*16*12*36*3];
__device__ float g_pool2[512*32*6*18*3];
__device__ float g_flat [512*64*81];     // (B, D,H,W,C)
__device__ float g_mean [512*64];
__device__ unsigned g_af[72576];         // precomputed tf32 A-fragments (all stages)

// ---------------- tf32 helpers ----------------
__device__ __forceinline__ unsigned f2tf(float f) {
    unsigned r; asm("cvt.rna.tf32.f32 %0, %1;" : "=r"(r) : "f"(f)); return r;
}
__device__ __forceinline__ void mma_tf32(float c[4],
    unsigned a0, unsigned a1, unsigned a2, unsigned a3,
    unsigned b0, unsigned b1)
{
    asm("mma.sync.aligned.m16n8k8.row.col.f32.tf32.tf32.f32 "
        "{%0,%1,%2,%3},{%4,%5,%6,%7},{%8,%9},{%0,%1,%2,%3};"
        : "+f"(c[0]), "+f"(c[1]), "+f"(c[2]), "+f"(c[3])
        : "r"(a0), "r"(a1), "r"(a2), "r"(a3), "r"(b0), "r"(b1));
}

// ---------------- A-fragment precompute (runs once, tiny) ----------------
template<int ICT,int NG,int MT>
__global__ void prep_af(const float* __restrict__ wgt, unsigned* __restrict__ dst, int total)
{
    int idx = blockIdx.x*256 + threadIdx.x;
    if (idx >= total) return;
    constexpr int AFRAG = MT*27*128;
    int i  = idx % AFRAG;
    int zg = idx / AFRAG;          // z*NG + g
    int g  = zg % NG, z = zg / NG;
    int j = i & 3, ln = (i >> 2) & 31, kt = i >> 7;
    int ks = kt % 27, mt = kt / 27;
    int llq = ln & 3, llg = ln >> 2;
    int icl = llq + (j >> 1) * 4;
    int oc  = z*(MT*16) + mt*16 + llg + (j & 1) * 8;
    int ic  = g*8 + icl;
    float v = (ic < ICT) ? __ldg(wgt + ((size_t)oc*ICT + ic)*27 + ks) : 0.f;
    dst[idx] = f2tf(v);
}

// ------- conv3d(3x3x3,pad1)+relu+maxpool(2,2,1), implicit GEMM, tap-major K -------
template<int ICT,int NG,int DIN,int HT,int HIN,int OCB,int OCTOT,int NSUB,bool FLAT>
__global__ __launch_bounds__(256)
void conv_tc(const float* __restrict__ in, const unsigned* __restrict__ af,
             const float* __restrict__ bias, float* __restrict__ outp)
{
    constexpr int ICG = 8, KS = 27;
    constexpr int MT  = OCB/16;
    constexpr int SH  = 5, SD = (HT+2)*5;
    constexpr int SIC_RAW = (DIN+2)*SD;
    constexpr int SIC = ((SIC_RAW + 23)/32)*32 + 8;   // ≡ 8 (mod 32)
    constexpr int N   = DIN*HT*3;
    constexpr int NJ  = (N + NSUB*8 - 1)/(NSUB*8);
    static_assert(NJ <= 8, "one n-block per warp");
    constexpr int NPAD = NJ*NSUB*8;
    constexpr int DOUT = DIN/2, HTO = HT/2, HOUT = HIN/2;
    constexpr int AFRAG = MT*KS*128;
    constexpr int XSW   = ICG*SIC;

    extern __shared__ unsigned smu[];
    unsigned* Af = smu;                   // AFRAG words
    unsigned* Xs = smu + AFRAG;           // XSW words
    float*    C  = (float*)smu;           // overlay: used only after final sync

    const int tid  = threadIdx.x;
    const int b    = blockIdx.x;
    const int ht   = blockIdx.y;
    const int ocb0 = blockIdx.z * OCB;
    const int warp = tid >> 5, lane = tid & 31, lq = lane & 3, lg = lane >> 2;

    float acc[MT][NSUB][4];
    #pragma unroll
    for (int mt = 0; mt < MT; mt++)
        #pragma unroll
        for (int s = 0; s < NSUB; s++)
            { acc[mt][s][0]=0.f; acc[mt][s][1]=0.f; acc[mt][s][2]=0.f; acc[mt][s][3]=0.f; }

    // per-warp B base addresses (n-block = warp)
    int bb0[NSUB], bb1[NSUB];
    {
        int n0 = warp * NSUB * 8;
        #pragma unroll
        for (int s = 0; s < NSUB; s++) {
            int n = n0 + s*8 + lg;
            int base = 0;
            if (n < N) {
                int d = n / (HT*3); int r = n % (HT*3);
                base = d*SD + (r/3)*SH + (r%3);
            }
            bb0[s] = base + lq*SIC;
            bb1[s] = base + (lq+4)*SIC;
        }
    }

    // ---- zero Xs once (halo/pad identical across k-groups) ----
    for (int i = tid; i < XSW/4; i += 256) ((uint4*)Xs)[i] = make_uint4(0u,0u,0u,0u);
    __syncthreads();

    #pragma unroll 1
    for (int g = 0; g < NG; g++) {
        if (g) __syncthreads();
        // ---- A fragments: linear copy from precomputed global ----
        {
            const uint4* asrc = (const uint4*)(af + (size_t)(blockIdx.z*NG + g)*AFRAG);
            for (int i = tid; i < AFRAG/4; i += 256) ((uint4*)Af)[i] = asrc[i];
        }
        // ---- X interior rows: 3 coalesced loads per (ic,d,hh) row ----
        {
            const int ICC = (ICT - g*ICG < ICG) ? (ICT - g*ICG) : ICG;
            const int ROWS = ICC * DIN * (HT+2);
            const float* inb = in + ((size_t)b*ICT + g*ICG) * DIN * HIN * 3;
            for (int r = tid; r < ROWS; r += 256) {
                int ic  = r / (DIN*(HT+2));
                int rem = r % (DIN*(HT+2));
                int d   = rem / (HT+2);
                int hh  = rem % (HT+2);
                int h   = ht*HT + hh - 1;
                if ((unsigned)h < (unsigned)HIN) {
                    const float* src = inb + ((size_t)ic*DIN + d)*(HIN*3) + h*3;
                    unsigned* dstp = Xs + ic*SIC + (d+1)*SD + hh*5 + 1;
                    dstp[0] = f2tf(src[0]);
                    dstp[1] = f2tf(src[1]);
                    dstp[2] = f2tf(src[2]);
                }
            }
        }
        __syncthreads();

        if (warp < NJ) {
            const uint4* Afr = (const uint4*)Af + lane;
            #pragma unroll
            for (int ks = 0; ks < KS; ks++) {
                uint4 a[MT];
                #pragma unroll
                for (int mt = 0; mt < MT; mt++) a[mt] = Afr[(mt*KS + ks)*32];
                const int toff = (ks/9)*SD + ((ks/3)%3)*SH + (ks%3);
                #pragma unroll
                for (int s = 0; s < NSUB; s++) {
                    unsigned b0 = Xs[bb0[s] + toff];
                    unsigned b1 = Xs[bb1[s] + toff];
                    #pragma unroll
                    for (int mt = 0; mt < MT; mt++)
                        mma_tf32(acc[mt][s], a[mt].x, a[mt].y, a[mt].z, a[mt].w, b0, b1);
                }
            }
        }
    }
    __syncthreads();   // all Af/Xs reads done -> C may overlay

    if (warp < NJ) {
        int n0 = warp * NSUB * 8;
        #pragma unroll
        for (int mt = 0; mt < MT; mt++) {
            int m0 = mt*16;
            #pragma unroll
            for (int s = 0; s < NSUB; s++) {
                int nn = n0 + s*8 + 2*lq;
                C[(m0+lg  )*NPAD + nn  ] = acc[mt][s][0];
                C[(m0+lg  )*NPAD + nn+1] = acc[mt][s][1];
                C[(m0+lg+8)*NPAD + nn  ] = acc[mt][s][2];
                C[(m0+lg+8)*NPAD + nn+1] = acc[mt][s][3];
            }
        }
    }
    __syncthreads();

    // ---- pool(2,2,1) + bias + relu + store ----
    constexpr int TOT = OCB * DOUT * HTO * 3;
    for (int i = tid; i < TOT; i += 256) {
        int oc = i / (DOUT*HTO*3); int r = i % (DOUT*HTO*3);
        int dp = r / (HTO*3); int r2 = r % (HTO*3); int hp = r2/3, w = r2%3;
        const float* Cr = C + (size_t)oc*NPAD;
        int n00 = ((2*dp)*HT + 2*hp)*3 + w;
        float v = fmaxf(fmaxf(Cr[n00], Cr[n00+3]),
                        fmaxf(Cr[n00+HT*3], Cr[n00+HT*3+3]));
        int ocg = ocb0 + oc;
        v = fmaxf(v + __ldg(bias + ocg), 0.f);
        int hpg = ht*HTO + hp;
        if (FLAT)
            outp[(size_t)b*(DOUT*HOUT*3*OCTOT) + ((dp*HOUT + hpg)*3 + w)*OCTOT + ocg] = v;
        else
            outp[((size_t)b*OCTOT + ocg)*(DOUT*HOUT*3) + (dp*HOUT + hpg)*3 + w] = v;
    }
}

// ---------------- mean over the 81 spatial positions ----------------
__global__ void mean_kernel()
{
    int b = blockIdx.x, c = threadIdx.x;
    const float* f = g_flat + (size_t)b * 5184 + c;
    float s = 0.f;
    #pragma unroll
    for (int p = 0; p < 81; p++) s += f[p * 64];
    g_mean[b * 64 + c] = s * (1.f / 81.f);
}

// ---------------- smem-tiled matvec: out[n=t][r=0..3] += W[n][k] * X[k][r] ----------------
template<int K, int KT>
__device__ __forceinline__ void matvec4(const float* __restrict__ W,
                                        const float* __restrict__ Xsh,
                                        float* __restrict__ Wsh,
                                        float acc[4], int t)
{
    constexpr int RS = KT + 4;
    constexpr int QP = KT / 4;
    for (int kt = 0; kt < K; kt += KT) {
        __syncthreads();
        #pragma unroll
        for (int i = 0; i < QP; i++) {
            int idx = t + i * 256;
            int n   = idx / QP;
            int kq  = idx % QP;
            *(float4*)(Wsh + n * RS + kq * 4) =
                *(const float4*)(W + (size_t)n * K + kt + kq * 4);
        }
        __syncthreads();
        #pragma unroll
        for (int kk = 0; kk < KT; kk += 4) {
            float4 wv = *(const float4*)(Wsh + t * RS + kk);
            float4 x0 = *(const float4*)(Xsh + (kt + kk + 0) * 4);
            float4 x1 = *(const float4*)(Xsh + (kt + kk + 1) * 4);
            float4 x2 = *(const float4*)(Xsh + (kt + kk + 2) * 4);
            float4 x3 = *(const float4*)(Xsh + (kt + kk + 3) * 4);
            acc[0] += wv.x * x0.x; acc[1] += wv.x * x0.y; acc[2] += wv.x * x0.z; acc[3] += wv.x * x0.w;
            acc[0] += wv.y * x1.x; acc[1] += wv.y * x1.y; acc[2] += wv.y * x1.z; acc[3] += wv.y * x1.w;
            acc[0] += wv.z * x2.x; acc[1] += wv.z * x2.y; acc[2] += wv.z * x2.z; acc[3] += wv.z * x2.w;
            acc[0] += wv.w * x3.x; acc[1] += wv.w * x3.y; acc[2] += wv.w * x3.z; acc[3] += wv.w * x3.w;
        }
    }
}

// ---------------- fused RNN decoder + linear head (co-scheduled, 2 CTA/SM) ----------------
// blocks 0..127: RNN (4 batch rows each).  blocks 128..255: head (4 rows each, X streamed).
__global__ __launch_bounds__(256)
void tail_kernel(const float* __restrict__ whh1, const float* __restrict__ wih2,
                 const float* __restrict__ whh2,
                 const float* __restrict__ w_init_h,  const float* __restrict__ b_init_h,
                 const float* __restrict__ w_init_h2, const float* __restrict__ b_init_h2,
                 const float* __restrict__ wih1, const float* __restrict__ bih1,
                 const float* __restrict__ bhh1,
                 const float* __restrict__ bih2, const float* __restrict__ bhh2,
                 const float* __restrict__ w_fc, const float* __restrict__ b_fc,
                 const float* __restrict__ w_lin1, const float* __restrict__ b_lin1,
                 const float* __restrict__ w_lin2, const float* __restrict__ b_lin2,
                 float* __restrict__ preds, float* __restrict__ outc)
{
    extern __shared__ float sm[];
    const int t = threadIdx.x;

    if (blockIdx.x < 128) {
        // ================= RNN path (smem: 4352 + 17408 = 21760 floats = 87040 B) =====
        float* me   = sm;
        float* hS   = sm + 256;
        float* h2S  = sm + 1280;
        float* ihcS = sm + 2304;
        float* hnS  = sm + 3328;
        float* Wsh  = sm + 4352;     // 256*68 floats

        const int r0 = blockIdx.x * 4;

        { int r = t & 3, k = t >> 2;
          me[k*4 + r] = g_mean[(size_t)(r0 + r) * 64 + k]; }

        float a[4] = {0,0,0,0};
        matvec4<64,64>(w_init_h, me, Wsh, a, t);
        float c[4] = {0,0,0,0};
        matvec4<64,64>(wih1, me, Wsh, c, t);
        {
            float bh = __ldg(b_init_h + t);
            float bi = __ldg(bih1 + t) + __ldg(bhh1 + t);
            #pragma unroll
            for (int r = 0; r < 4; r++) { hS[t*4 + r] = a[r] + bh; ihcS[t*4 + r] = c[r] + bi; }
        }
        float a2[4] = {0,0,0,0};
        matvec4<256,64>(w_init_h2, hS, Wsh, a2, t);
        {
            float b2 = __ldg(b_init_h2 + t);
            #pragma unroll
            for (int r = 0; r < 4; r++) h2S[t*4 + r] = a2[r] + b2;
        }
        const float bi2 = __ldg(bih2 + t) + __ldg(bhh2 + t);
        const float bfc = __ldg(b_fc);

        for (int step = 0; step < 23; ++step) {
            float ah[4] = {0,0,0,0};
            matvec4<256,64>(whh1, hS, Wsh, ah, t);
            #pragma unroll
            for (int r = 0; r < 4; r++) hnS[t*4 + r] = tanhf(ihcS[t*4 + r] + ah[r]);
            float u[4] = {0,0,0,0};
            matvec4<256,64>(wih2, hnS, Wsh, u, t);
            float v[4] = {0,0,0,0};
            matvec4<256,64>(whh2, h2S, Wsh, v, t);
            __syncthreads();
            #pragma unroll
            for (int r = 0; r < 4; r++) {
                h2S[t*4 + r] = tanhf(u[r] + v[r] + bi2);
                hS[t*4 + r]  = hnS[t*4 + r];
            }
            __syncthreads();
            if (t < 128) {
                int r = t >> 5, lane = t & 31;
                float s = 0.f;
                #pragma unroll
                for (int k = lane; k < 256; k += 32) s += __ldg(w_fc + k) * h2S[k*4 + r];
                #pragma unroll
                for (int off = 16; off; off >>= 1) s += __shfl_down_sync(0xffffffffu, s, off);
                if (lane == 0) preds[(size_t)(r0 + r) * 23 + step] = s + bfc;
            }
        }
    } else {
        // ================= head path: X streamed per 64-tile =================
        // smem: xt 256 + thS 1024 + Wsh 17408 = 18688 floats = 74752 B
        float* xt  = sm;             // [64][4]
        float* thS = sm + 256;       // 1024
        float* Wsh = sm + 1280;      // 256*68
        const int r0 = (blockIdx.x - 128) * 4;
        constexpr int RS = 68;

        float a[4] = {0,0,0,0};
        // k = t>>2 (0..63), r = t&3 — each thread stages one element per tile
        const int xk = t >> 2, xr = t & 3;
        const float* xsrc = g_flat + (size_t)(r0 + xr) * 5184 + xk;

        #pragma unroll 1
        for (int kt = 0; kt < 5184; kt += 64) {
            __syncthreads();
            // stage W tile [256][64]
            #pragma unroll
            for (int i = 0; i < 16; i++) {
                int idx = t + i * 256;
                int n   = idx >> 4;
                int kq  = idx & 15;
                *(float4*)(Wsh + n * RS + kq * 4) =
                    *(const float4*)(w_lin1 + (size_t)n * 5184 + kt + kq * 4);
            }
            // stage X tile [64][4]
            xt[xk*4 + xr] = xsrc[kt];
            __syncthreads();
            #pragma unroll
            for (int kk = 0; kk < 64; kk += 4) {
                float4 wv = *(const float4*)(Wsh + t * RS + kk);
                float4 x0 = *(const float4*)(xt + (kk + 0) * 4);
                float4 x1 = *(const float4*)(xt + (kk + 1) * 4);
                float4 x2 = *(const float4*)(xt + (kk + 2) * 4);
                float4 x3 = *(const float4*)(xt + (kk + 3) * 4);
                acc_fma:
                a[0] += wv.x * x0.x; a[1] += wv.x * x0.y; a[2] += wv.x * x0.z; a[3] += wv.x * x0.w;
                a[0] += wv.y * x1.x; a[1] += wv.y * x1.y; a[2] += wv.y * x1.z; a[3] += wv.y * x1.w;
                a[0] += wv.z * x2.x; a[1] += wv.z * x2.y; a[2] += wv.z * x2.z; a[3] += wv.z * x2.w;
                a[0] += wv.w * x3.x; a[1] += wv.w * x3.y; a[2] += wv.w * x3.z; a[3] += wv.w * x3.w;
            }
        }

        float bl = __ldg(b_lin1 + t);
        __syncthreads();
        #pragma unroll
        for (int r = 0; r < 4; r++) thS[t*4 + r] = tanhf(a[r] + bl);
        __syncthreads();

        if (t < 48) {
            int n = t % 12, r = t / 12;
            float s = 0.f;
            #pragma unroll 4
            for (int k = 0; k < 256; k++) s += __ldg(w_lin2 + n*256 + k) * thS[k*4 + r];
            outc[(size_t)(r0 + r) * 12 + n] = s + __ldg(b_lin2 + n);
        }
    }
}

// ---------------- launch ----------------
extern "C" void kernel_launch(void* const* d_in, const int* in_sizes, int n_in,
                              void* d_out, int out_size)
{
    const float* x    = (const float*)d_in[0];
    const float* w1   = (const float*)d_in[1];
    const float* b1   = (const float*)d_in[2];
    const float* w2   = (const float*)d_in[3];
    const float* b2   = (const float*)d_in[4];
    const float* w3   = (const float*)d_in[5];
    const float* b3   = (const float*)d_in[6];
    const float* wih1 = (const float*)d_in[7];
    const float* whh1 = (const float*)d_in[8];
    const float* bih1 = (const float*)d_in[9];
    const float* bhh1 = (const float*)d_in[10];
    const float* wih2 = (const float*)d_in[11];
    const float* whh2 = (const float*)d_in[12];
    const float* bih2 = (const float*)d_in[13];
    const float* bhh2 = (const float*)d_in[14];
    const float* w_init_h  = (const float*)d_in[15];
    const float* b_init_h  = (const float*)d_in[16];
    const float* w_init_h2 = (const float*)d_in[17];
    const float* b_init_h2 = (const float*)d_in[18];
    const float* w_fc  = (const float*)d_in[19];
    const float* b_fc  = (const float*)d_in[20];
    const float* w_lin1 = (const float*)d_in[21];
    const float* b_lin1 = (const float*)d_in[22];
    const float* w_lin2 = (const float*)d_in[23];
    const float* b_lin2 = (const float*)d_in[24];
    float* out = (float*)d_out;

    float *p1, *p2, *pf;
    unsigned* af;
    cudaGetSymbolAddress((void**)&p1, g_pool1);
    cudaGetSymbolAddress((void**)&p2, g_pool2);
    cudaGetSymbolAddress((void**)&pf, g_flat);
    cudaGetSymbolAddress((void**)&af, g_af);

    // idx 0: prep stage-1 A-fragments
    prep_af<6,1,1><<<14, 256>>>(w1, af, 3456);

    // idx 1: stage 1: ICT=6, NG=1, D24, HT8, H72, OC16, NSUB=9  smem=56064B -> 4 CTA/SM
    auto k1 = conv_tc<6,1,24,8,72,16,16,9,false>;
    cudaFuncSetAttribute(k1, cudaFuncAttributeMaxDynamicSharedMemorySize, 56064);
    k1<<<dim3(512,9,1), 256, 56064>>>(x, af, b1, p1);

    // idx 2: prep stage-2 A-fragments
    prep_af<16,2,2><<<54, 256>>>(w2, af + 3456, 13824);

    // idx 3 (profiled): stage 2: ICT=16, NG=2, D12, HT12, H36, OC32, NSUB=7  smem=59648B
    auto k2 = conv_tc<16,2,12,12,36,32,32,7,false>;
    cudaFuncSetAttribute(k2, cudaFuncAttributeMaxDynamicSharedMemorySize, 59648);
    k2<<<dim3(512,3,1), 256, 59648>>>(p1, af + 3456, b2, p2);

    // idx 4: prep stage-3 A-fragments
    prep_af<32,4,2><<<216,256>>>(w3, af + 17280, 55296);

    // idx 5: stage 3: ICT=32, NG=4, D6, HT18, H18, OC 2x32, NSUB=6  smem=53504B
    auto k3 = conv_tc<32,4,6,18,18,32,64,6,true>;
    cudaFuncSetAttribute(k3, cudaFuncAttributeMaxDynamicSharedMemorySize, 53504);
    k3<<<dim3(512,1,2), 256, 53504>>>(p2, af + 17280, b3, pf);

    // idx 6: mean
    mean_kernel<<<512, 64>>>();

    // idx 7: fused RNN + head: 256 blocks, 87040B smem -> 2 CTA/SM, single wave
    cudaFuncSetAttribute(tail_kernel, cudaFuncAttributeMaxDynamicSharedMemorySize, 87040);
    tail_kernel<<<256, 256, 87040>>>(whh1, wih2, whh2,
                                     w_init_h, b_init_h, w_init_h2, b_init_h2,
                                     wih1, bih1, bhh1, bih2, bhh2,
                                     w_fc, b_fc,
                                     w_lin1, b_lin1, w_lin2, b_lin2,
                                     out, out + 512 * 23);
}